// round 15
// baseline (speedup 1.0000x reference)
#include <cuda_runtime.h>

#define NMAX 64
#define OUTD 224
#define HW   50176          // 224*224
#define FC   2048
#define FHW  49             // 7*7
#define RMAX 8              // max runs/row (true bound 4: rows are piecewise-linear)
#define NRUNS (OUTD * RMAX) // 1792
#define NSLICE 4
#define TMAIN 896           // Phase C: 16 row-groups x 56 col-groups (4 cols each)
#define BAND 32             // crop: output rows per block
#define SROWS 34            // max source rows per band (31 span + x1 + margin)

// global scratch (no allocations allowed)
__device__ float d_part[NMAX * NSLICE * FHW];
__device__ __align__(16) float2 d_tr[NMAX * OUTD];   // per-(n,row): (x0 bits, wx)
__device__ __align__(16) float2 d_tc[NMAX * OUTD];   // per-(n,col): (y0 bits, wy)

// ---------------- union-find over run ids in shared memory ----------------
__device__ __forceinline__ int uf_find(int* P, int i) {
    int p = P[i];
    while (p != i) {
        int gp = P[p];
        if (gp != p) P[i] = gp;   // path halving (benign race)
        i = p; p = gp;
    }
    return i;
}

__device__ __forceinline__ void uf_union(int* P, int a, int b) {
    int ra = uf_find(P, a), rb = uf_find(P, b);
    while (ra != rb) {
        if (ra < rb) { int t = ra; ra = rb; rb = t; }
        int old = atomicCAS(&P[ra], ra, rb);   // link larger root under smaller
        if (old == ra) break;
        ra = uf_find(P, old);
        rb = uf_find(P, rb);
    }
}

// ---------------- kernel 1: per-slice channel-max of |feat| (LDG.128, atomic tail) ----------------
// grid (NSLICE=4, N) = 256 CTAs, block 784. Slice = 512 ch x 49 pos = 6272 float4.
// k-stride = 784 float4 = 64 whole channels -> lane j keeps position (4t+j) % 49.
// Tail: shared atomicMax on float bit patterns (all values >= 0).
__global__ __launch_bounds__(784) void k_featmax(const float* __restrict__ feat)
{
    __shared__ int sMax[FHW];
    const int n = blockIdx.y, s = blockIdx.x;
    const int t = threadIdx.x;
    if (t < FHW) sMax[t] = 0;
    __syncthreads();

    const float4* base = reinterpret_cast<const float4*>(
        feat + (size_t)n * (FC * FHW) + (size_t)s * (FC / NSLICE) * FHW) + t;

    float4 v[8];
    #pragma unroll
    for (int k = 0; k < 8; k++)
        v[k] = base[k * 784];                 // 8 x LDG.128 in flight

    float m0 = 0.f, m1 = 0.f, m2 = 0.f, m3 = 0.f;
    #pragma unroll
    for (int k = 0; k < 8; k++) {
        m0 = fmaxf(m0, fabsf(v[k].x));
        m1 = fmaxf(m1, fabsf(v[k].y));
        m2 = fmaxf(m2, fabsf(v[k].z));
        m3 = fmaxf(m3, fabsf(v[k].w));
    }

    int p0 = (4 * t) % 49;
    int p1 = (p0 + 1 < 49) ? p0 + 1 : 0;
    int p2 = (p1 + 1 < 49) ? p1 + 1 : 0;
    int p3 = (p2 + 1 < 49) ? p2 + 1 : 0;
    atomicMax(&sMax[p0], __float_as_int(m0));
    atomicMax(&sMax[p1], __float_as_int(m1));
    atomicMax(&sMax[p2], __float_as_int(m2));
    atomicMax(&sMax[p3], __float_as_int(m3));
    __syncthreads();

    if (t < FHW)
        d_part[(n * NSLICE + s) * FHW + t] = __int_as_float(sMax[t]);
}

// ---------------- kernel 2: normalize + upsample + mask + CCL + bbox + tables (R13 proven) ----------------
__global__ __launch_bounds__(TMAIN, 1) void k_main(
    float* __restrict__ outHeat,
    float* __restrict__ outCoords)
{
    extern __shared__ int S[];     // sSE[NRUNS], P[NRUNS], cnt[NRUNS]  (21 KB)
    int* sSE = S;
    int* P   = S + NRUNS;
    int* cnt = S + 2 * NRUNS;

    __shared__ float sH[FHW];
    __shared__ int   sX0[OUTD], sX1[OUTD];
    __shared__ float sWt[OUTD];
    __shared__ __align__(16) float sTAc[7 * OUTD];            // dedup'd y-blend table
    __shared__ __align__(4) unsigned char sMaskB[OUTD * 28];  // 224 bits/row as bytes
    __shared__ int   sRunCnt[OUTD];
    __shared__ float sMn, sMx;
    __shared__ int   sBC[28], sBR[28];
    __shared__ int   sBest, sBestCnt, sRmin, sRmax, sCmin, sCmax;
    __shared__ int4  sBox;

    const int n   = blockIdx.x;
    const int tid = threadIdx.x;
    const int c4  = tid % 56;          // 4-col group (warp pairs share a row)
    const int rg  = tid / 56;          // 0..15
    const int c0  = c4 * 4;

    // Phase B: gather partial maxes, interp tables, init UF state
    if (tid < FHW) {
        const float* pp = d_part + n * NSLICE * FHW + tid;
        float m = pp[0];
        #pragma unroll
        for (int j = 1; j < NSLICE; j++) m = fmaxf(m, pp[j * FHW]);
        sH[tid] = m;
    }
    if (tid >= 64 && tid < 64 + OUTD) {   // exact reference arithmetic
        int i = tid - 64;
        float g  = (float)i / 223.0f;
        float xs = __fmul_rn(g, 6.0f);
        int x0 = (int)floorf(xs);
        x0 = min(max(x0, 0), 6);
        sX0[i] = x0;
        sX1[i] = min(x0 + 1, 6);
        sWt[i] = __fsub_rn(xs, (float)x0);
    }
    for (int g = tid; g < NRUNS; g += TMAIN) { P[g] = g; cnt[g] = 0; }
    if (tid == 0) { sRmin = HW; sRmax = -1; sCmin = HW; sCmax = -1; }
    __syncthreads();
    if (tid == 0) {
        float mn = sH[0], mx = sH[0];
        for (int j = 1; j < FHW; j++) { mn = fminf(mn, sH[j]); mx = fmaxf(mx, sH[j]); }
        sMn = mn; sMx = mx;
    }
    __syncthreads();
    if (tid < FHW) sH[tid] = (sH[tid] - sMn) / (sMx - sMn);
    __syncthreads();

    // Phase C0: dedup'd column blend table
    if (tid < OUTD) {
        int y0 = sX0[tid], y1 = sX1[tid];
        float wy = sWt[tid], iwy = __fsub_rn(1.f, wy);
        #pragma unroll
        for (int k = 0; k < 7; k++)
            sTAc[k * OUTD + tid] =
                __fadd_rn(__fmul_rn(iwy, sH[k * 7 + y0]), __fmul_rn(wy, sH[k * 7 + y1]));
    }
    __syncthreads();

    // Phase C: row blend, float4 heat write, nibble-packed mask (14 iterations)
    float* oh = outHeat + (size_t)n * HW;
    #pragma unroll
    for (int i = 0; i < 14; i++) {
        int r = i * 16 + rg;
        int x0 = sX0[r], x1 = sX1[r];
        float wx = sWt[r], iwx = __fsub_rn(1.f, wx);
        float4 a = reinterpret_cast<const float4*>(sTAc + x0 * OUTD)[c4];   // LDS.128
        float4 b = reinterpret_cast<const float4*>(sTAc + x1 * OUTD)[c4];
        float4 v;
        v.x = __fadd_rn(__fmul_rn(iwx, a.x), __fmul_rn(wx, b.x));
        v.y = __fadd_rn(__fmul_rn(iwx, a.y), __fmul_rn(wx, b.y));
        v.z = __fadd_rn(__fmul_rn(iwx, a.z), __fmul_rn(wx, b.z));
        v.w = __fadd_rn(__fmul_rn(iwx, a.w), __fmul_rn(wx, b.w));
        *reinterpret_cast<float4*>(oh + r * OUTD + c0) = v;
        unsigned nib = (unsigned)(v.x > 0.7f) | ((unsigned)(v.y > 0.7f) << 1)
                     | ((unsigned)(v.z > 0.7f) << 2) | ((unsigned)(v.w > 0.7f) << 3);
        unsigned other = __shfl_xor_sync(0xffffffffu, nib, 1);   // partner c4^1, same row
        if ((tid & 1) == 0)
            sMaskB[r * 28 + (c4 >> 1)] = (unsigned char)(nib | (other << 4));
    }
    __syncthreads();

    const unsigned* sMask = reinterpret_cast<const unsigned*>(sMaskB);

    // Phase D: per-row run extraction
    if (tid < OUTD) {
        int r = tid, base = r * 7, cntR = 0, pos = 0;
        while (pos < 224 && cntR < RMAX) {
            int w = pos >> 5;
            unsigned m = sMask[base + w] & (0xffffffffu << (pos & 31));
            while (m == 0 && ++w < 7) m = sMask[base + w];
            if (m == 0) break;
            int start = (w << 5) + __ffs(m) - 1;
            unsigned inv = (~sMask[base + w]) & (0xffffffffu << (start & 31));
            int w2 = w;
            while (inv == 0 && ++w2 < 7) inv = ~sMask[base + w2];
            int end = (w2 == 7) ? 223 : ((w2 << 5) + __ffs(inv) - 2);
            sSE[r * RMAX + cntR] = (start << 16) | end;
            cntR++;
            pos = end + 2;
        }
        sRunCnt[r] = cntR;
    }
    __syncthreads();

    // Phase E: union overlapping runs in adjacent rows (8-connectivity)
    if (tid < OUTD - 1) {
        int r = tid;
        int ca = sRunCnt[r], cb = sRunCnt[r + 1];
        int i = 0, j = 0;
        while (i < ca && j < cb) {
            int A = sSE[r * RMAX + i];        int a0 = A >> 16, a1 = A & 0xffff;
            int B = sSE[(r + 1) * RMAX + j];  int b0 = B >> 16, b1 = B & 0xffff;
            if (b0 <= a1 + 1 && a0 <= b1 + 1)
                uf_union(P, r * RMAX + i, (r + 1) * RMAX + j);
            if (a1 <= b1) i++; else j++;
        }
    }
    __syncthreads();

    // Phase F: pixel counts per component (shared atomics)
    for (int g = tid; g < NRUNS; g += TMAIN) {
        int row = g >> 3, slot = g & (RMAX - 1);
        if (slot < sRunCnt[row]) {
            int A = sSE[g];
            atomicAdd(&cnt[uf_find(P, g)], (A & 0xffff) - (A >> 16) + 1);
        }
    }
    __syncthreads();

    // Phase G: argmax (count, tie -> smallest root id)
    {
        int bc = 0, br = 0x7fffffff;
        for (int g = tid; g < NRUNS; g += TMAIN) {
            int row = g >> 3, slot = g & (RMAX - 1);
            if (slot < sRunCnt[row]) {
                int cc = cnt[g];
                if (cc > bc || (cc == bc && g < br)) { bc = cc; br = g; }
            }
        }
        #pragma unroll
        for (int off = 16; off; off >>= 1) {
            int oc  = __shfl_down_sync(0xffffffffu, bc, off);
            int orr = __shfl_down_sync(0xffffffffu, br, off);
            if (oc > bc || (oc == bc && orr < br)) { bc = oc; br = orr; }
        }
        if ((tid & 31) == 0) { sBC[tid >> 5] = bc; sBR[tid >> 5] = br; }
        __syncthreads();
        if (tid == 0) {
            bc = sBC[0]; br = sBR[0];
            for (int j = 1; j < TMAIN / 32; j++) {
                if (sBC[j] > bc || (sBC[j] == bc && sBR[j] < br)) { bc = sBC[j]; br = sBR[j]; }
            }
            sBest = br; sBestCnt = bc;
        }
    }
    __syncthreads();

    // Phase H: bbox of largest component
    if (sBestCnt > 0) {
        int best = sBest;
        int rmin = HW, rmax = -1, cmin = HW, cmax = -1;
        for (int g = tid; g < NRUNS; g += TMAIN) {
            int row = g >> 3, slot = g & (RMAX - 1);
            if (slot < sRunCnt[row] && uf_find(P, g) == best) {
                int A = sSE[g];
                rmin = min(rmin, row); rmax = max(rmax, row);
                cmin = min(cmin, A >> 16); cmax = max(cmax, A & 0xffff);
            }
        }
        if (rmax >= 0) {
            atomicMin(&sRmin, rmin); atomicMax(&sRmax, rmax);
            atomicMin(&sCmin, cmin); atomicMax(&sCmax, cmax);
        }
    }
    __syncthreads();

    if (tid == 0) {
        int xmin = sRmin, xmax = sRmax, ymin = sCmin, ymax = sCmax;
        if (sBestCnt <= 0 || xmax < 0) { xmin = 0; ymin = 0; xmax = OUTD - 1; ymax = OUTD - 1; }
        sBox = make_int4(xmin, xmax, ymin, ymax);
        float* co = outCoords + n * 4;
        co[0] = (float)ymin; co[1] = (float)xmin;    // torch order [ymin,xmin,ymax,xmax]
        co[2] = (float)ymax; co[3] = (float)xmax;
    }
    __syncthreads();

    // Phase I: crop interpolation tables
    if (tid < OUTD) {
        int4 bx = sBox;
        int i = tid;
        float g = (float)i / 223.0f;
        int Lx = max(bx.y - bx.x, 1);
        float xs = __fadd_rn((float)bx.x, __fmul_rn(g, (float)(Lx - 1)));
        int x0 = min(max((int)floorf(xs), 0), 223);
        d_tr[n * OUTD + i] = make_float2(__int_as_float(x0), __fsub_rn(xs, (float)x0));
        int Ly = max(bx.w - bx.z, 1);
        float ys = __fadd_rn((float)bx.z, __fmul_rn(g, (float)(Ly - 1)));
        int y0 = min(max((int)floorf(ys), 0), 223);
        d_tc[n * OUTD + i] = make_float2(__int_as_float(y0), __fsub_rn(ys, (float)y0));
    }
}

// ---------------- kernel 3: band-tiled crop with source-row pre-blend (R12 proven) ----------------
__global__ __launch_bounds__(224) void k_crop(const float* __restrict__ x,
                                              float* __restrict__ out)
{
    __shared__ __align__(16) float sImg[SROWS * OUTD + 4];
    __shared__ __align__(16) float sCB[SROWS * OUTD];       // col-blended source rows
    __shared__ float2 sTR[BAND];
    __shared__ int sLo, sRr;

    const int band = blockIdx.x, ch = blockIdx.y, n = blockIdx.z;
    const int tid = threadIdx.x;
    const int r0g = band * BAND;

    if (tid < BAND) sTR[tid] = d_tr[n * OUTD + r0g + tid];
    float2 tc = d_tc[n * OUTD + tid];            // this thread's column (phase A)
    const int y0 = __float_as_int(tc.x);
    const int y1 = min(y0 + 1, 223);
    const float wy = tc.y, iwy = __fsub_rn(1.f, wy);
    __syncthreads();
    if (tid == 0) {
        int lo = __float_as_int(sTR[0].x);
        int hi = min(__float_as_int(sTR[BAND - 1].x) + 1, 223);
        sLo = lo; sRr = hi - lo + 1;             // <= 33
    }
    __syncthreads();
    const int lo = sLo, R = sRr;

    const float* img = x + ((size_t)n * 3 + ch) * HW + lo * OUTD;
    for (int i = tid; i < R * OUTD; i += 224)
        sImg[i] = __ldg(&img[i]);                // fully coalesced strip load
    __syncthreads();

    // Phase A: column blend per source row (column fixed per thread)
    for (int xr = 0; xr < R; xr++) {
        const float* row = sImg + xr * OUTD;
        sCB[xr * OUTD + tid] =
            __fadd_rn(__fmul_rn(iwy, row[y0]), __fmul_rn(wy, row[y1]));
    }
    __syncthreads();

    // Phase B: row blend, 4-col groups, LDS.128 + STG.128
    const int c4 = tid % 56, rg = tid / 56;      // (4 row-slots) x (56 col-groups)
    const int c0 = c4 * 4;
    float* o = out + ((size_t)n * 3 + ch) * HW;
    #pragma unroll
    for (int j = 0; j < BAND / 4; j++) {         // 8 iterations
        int rl = rg + j * 4;                     // local row 0..31
        float2 tr = sTR[rl];
        int x0 = __float_as_int(tr.x);
        int x0l = x0 - lo;
        int x1l = min(x0 + 1, 223) - lo;
        float wx = tr.y, iwx = __fsub_rn(1.f, wx);
        float4 a = reinterpret_cast<const float4*>(sCB + x0l * OUTD)[c4];
        float4 b = reinterpret_cast<const float4*>(sCB + x1l * OUTD)[c4];
        float4 res;
        res.x = __fadd_rn(__fmul_rn(iwx, a.x), __fmul_rn(wx, b.x));
        res.y = __fadd_rn(__fmul_rn(iwx, a.y), __fmul_rn(wx, b.y));
        res.z = __fadd_rn(__fmul_rn(iwx, a.z), __fmul_rn(wx, b.z));
        res.w = __fadd_rn(__fmul_rn(iwx, a.w), __fmul_rn(wx, b.w));
        *reinterpret_cast<float4*>(o + (r0g + rl) * OUTD + c0) = res;
    }
}

// ---------------- launch ----------------
extern "C" void kernel_launch(void* const* d_in, const int* in_sizes, int n_in,
                              void* d_out, int out_size)
{
    const float* x    = (const float*)d_in[0];   // (N,3,224,224)
    const float* feat = (const float*)d_in[1];   // (N,2048,7,7)
    float* out = (float*)d_out;

    int N = in_sizes[0] / (3 * HW);
    if (N > NMAX) N = NMAX;

    float* outCrop   = out;
    float* outHeat   = out + (size_t)N * 3 * HW;
    float* outCoords = out + (size_t)N * 3 * HW + (size_t)N * HW;

    k_featmax<<<dim3(NSLICE, N), 784>>>(feat);
    k_main   <<<N, TMAIN, 3 * NRUNS * sizeof(int)>>>(outHeat, outCoords);
    k_crop   <<<dim3(OUTD / BAND, 3, N), 224>>>(x, outCrop);
}

// round 16
// speedup vs baseline: 1.5435x; 1.5435x over previous
#include <cuda_runtime.h>

#define NMAX 64
#define OUTD 224
#define HW   50176          // 224*224
#define FC   2048
#define FHW  49             // 7*7
#define RMAX 8              // max runs/row (true bound 4: rows are piecewise-linear)
#define NRUNS (OUTD * RMAX) // 1792
#define NSLICE 8
#define TMAIN 896           // Phase C: 16 row-groups x 56 col-groups (4 cols each)
#define BAND 16             // crop: output rows per block
#define SROWS 18            // max source rows per band (15 span + x1 + margin)

// global scratch (no allocations allowed)
__device__ float d_part[NMAX * NSLICE * FHW];
__device__ __align__(16) float2 d_tr[NMAX * OUTD];   // per-(n,row): (x0 bits, wx)
__device__ __align__(16) float2 d_tc[NMAX * OUTD];   // per-(n,col): (y0 bits, wy)

// ---------------- union-find over run ids in shared memory ----------------
__device__ __forceinline__ int uf_find(int* P, int i) {
    int p = P[i];
    while (p != i) {
        int gp = P[p];
        if (gp != p) P[i] = gp;   // path halving (benign race)
        i = p; p = gp;
    }
    return i;
}

__device__ __forceinline__ void uf_union(int* P, int a, int b) {
    int ra = uf_find(P, a), rb = uf_find(P, b);
    while (ra != rb) {
        if (ra < rb) { int t = ra; ra = rb; rb = t; }
        int old = atomicCAS(&P[ra], ra, rb);   // link larger root under smaller
        if (old == ra) break;
        ra = uf_find(P, old);
        rb = uf_find(P, rb);
    }
}

// ---------------- kernel 1: per-slice channel-max of |feat| (R13 proven, CLOSED) ----------------
__global__ __launch_bounds__(784) void k_featmax(const float* __restrict__ feat)
{
    __shared__ float sP[16 * FHW];
    const int n = blockIdx.y, s = blockIdx.x;
    const int t = threadIdx.x;
    const float* base = feat + (size_t)n * (FC * FHW) + (size_t)s * (FC / NSLICE) * FHW + t;

    float m = 0.f;
    #pragma unroll
    for (int k = 0; k < (FC / NSLICE) / 16; k++)   // 16 coalesced loads
        m = fmaxf(m, fabsf(base[k * 16 * FHW]));
    sP[t] = m;
    __syncthreads();
    if (t < FHW) {
        float mm = sP[t];
        #pragma unroll
        for (int j = 1; j < 16; j++) mm = fmaxf(mm, sP[j * FHW + t]);
        d_part[(n * NSLICE + s) * FHW + t] = mm;
    }
}

// ---------------- kernel 2: normalize + upsample + mask + CCL + bbox + tables (R13 proven) ----------------
__global__ __launch_bounds__(TMAIN, 1) void k_main(
    float* __restrict__ outHeat,
    float* __restrict__ outCoords)
{
    extern __shared__ int S[];     // sSE[NRUNS], P[NRUNS], cnt[NRUNS]  (21 KB)
    int* sSE = S;
    int* P   = S + NRUNS;
    int* cnt = S + 2 * NRUNS;

    __shared__ float sH[FHW];
    __shared__ int   sX0[OUTD], sX1[OUTD];
    __shared__ float sWt[OUTD];
    __shared__ __align__(16) float sTAc[7 * OUTD];            // dedup'd y-blend table
    __shared__ __align__(4) unsigned char sMaskB[OUTD * 28];  // 224 bits/row as bytes
    __shared__ int   sRunCnt[OUTD];
    __shared__ float sMn, sMx;
    __shared__ int   sBC[28], sBR[28];
    __shared__ int   sBest, sBestCnt, sRmin, sRmax, sCmin, sCmax;
    __shared__ int4  sBox;

    const int n   = blockIdx.x;
    const int tid = threadIdx.x;
    const int c4  = tid % 56;          // 4-col group (warp pairs share a row)
    const int rg  = tid / 56;          // 0..15
    const int c0  = c4 * 4;

    // Phase B: gather partial maxes, interp tables, init UF state
    if (tid < FHW) {
        const float* pp = d_part + n * NSLICE * FHW + tid;
        float m = pp[0];
        #pragma unroll
        for (int j = 1; j < NSLICE; j++) m = fmaxf(m, pp[j * FHW]);
        sH[tid] = m;
    }
    if (tid >= 64 && tid < 64 + OUTD) {   // exact reference arithmetic
        int i = tid - 64;
        float g  = (float)i / 223.0f;
        float xs = __fmul_rn(g, 6.0f);
        int x0 = (int)floorf(xs);
        x0 = min(max(x0, 0), 6);
        sX0[i] = x0;
        sX1[i] = min(x0 + 1, 6);
        sWt[i] = __fsub_rn(xs, (float)x0);
    }
    for (int g = tid; g < NRUNS; g += TMAIN) { P[g] = g; cnt[g] = 0; }
    if (tid == 0) { sRmin = HW; sRmax = -1; sCmin = HW; sCmax = -1; }
    __syncthreads();
    if (tid == 0) {
        float mn = sH[0], mx = sH[0];
        for (int j = 1; j < FHW; j++) { mn = fminf(mn, sH[j]); mx = fmaxf(mx, sH[j]); }
        sMn = mn; sMx = mx;
    }
    __syncthreads();
    if (tid < FHW) sH[tid] = (sH[tid] - sMn) / (sMx - sMn);
    __syncthreads();

    // Phase C0: dedup'd column blend table
    if (tid < OUTD) {
        int y0 = sX0[tid], y1 = sX1[tid];
        float wy = sWt[tid], iwy = __fsub_rn(1.f, wy);
        #pragma unroll
        for (int k = 0; k < 7; k++)
            sTAc[k * OUTD + tid] =
                __fadd_rn(__fmul_rn(iwy, sH[k * 7 + y0]), __fmul_rn(wy, sH[k * 7 + y1]));
    }
    __syncthreads();

    // Phase C: row blend, float4 heat write, nibble-packed mask (14 iterations)
    float* oh = outHeat + (size_t)n * HW;
    #pragma unroll
    for (int i = 0; i < 14; i++) {
        int r = i * 16 + rg;
        int x0 = sX0[r], x1 = sX1[r];
        float wx = sWt[r], iwx = __fsub_rn(1.f, wx);
        float4 a = reinterpret_cast<const float4*>(sTAc + x0 * OUTD)[c4];   // LDS.128
        float4 b = reinterpret_cast<const float4*>(sTAc + x1 * OUTD)[c4];
        float4 v;
        v.x = __fadd_rn(__fmul_rn(iwx, a.x), __fmul_rn(wx, b.x));
        v.y = __fadd_rn(__fmul_rn(iwx, a.y), __fmul_rn(wx, b.y));
        v.z = __fadd_rn(__fmul_rn(iwx, a.z), __fmul_rn(wx, b.z));
        v.w = __fadd_rn(__fmul_rn(iwx, a.w), __fmul_rn(wx, b.w));
        *reinterpret_cast<float4*>(oh + r * OUTD + c0) = v;
        unsigned nib = (unsigned)(v.x > 0.7f) | ((unsigned)(v.y > 0.7f) << 1)
                     | ((unsigned)(v.z > 0.7f) << 2) | ((unsigned)(v.w > 0.7f) << 3);
        unsigned other = __shfl_xor_sync(0xffffffffu, nib, 1);   // partner c4^1, same row
        if ((tid & 1) == 0)
            sMaskB[r * 28 + (c4 >> 1)] = (unsigned char)(nib | (other << 4));
    }
    __syncthreads();

    const unsigned* sMask = reinterpret_cast<const unsigned*>(sMaskB);

    // Phase D: per-row run extraction
    if (tid < OUTD) {
        int r = tid, base = r * 7, cntR = 0, pos = 0;
        while (pos < 224 && cntR < RMAX) {
            int w = pos >> 5;
            unsigned m = sMask[base + w] & (0xffffffffu << (pos & 31));
            while (m == 0 && ++w < 7) m = sMask[base + w];
            if (m == 0) break;
            int start = (w << 5) + __ffs(m) - 1;
            unsigned inv = (~sMask[base + w]) & (0xffffffffu << (start & 31));
            int w2 = w;
            while (inv == 0 && ++w2 < 7) inv = ~sMask[base + w2];
            int end = (w2 == 7) ? 223 : ((w2 << 5) + __ffs(inv) - 2);
            sSE[r * RMAX + cntR] = (start << 16) | end;
            cntR++;
            pos = end + 2;
        }
        sRunCnt[r] = cntR;
    }
    __syncthreads();

    // Phase E: union overlapping runs in adjacent rows (8-connectivity)
    if (tid < OUTD - 1) {
        int r = tid;
        int ca = sRunCnt[r], cb = sRunCnt[r + 1];
        int i = 0, j = 0;
        while (i < ca && j < cb) {
            int A = sSE[r * RMAX + i];        int a0 = A >> 16, a1 = A & 0xffff;
            int B = sSE[(r + 1) * RMAX + j];  int b0 = B >> 16, b1 = B & 0xffff;
            if (b0 <= a1 + 1 && a0 <= b1 + 1)
                uf_union(P, r * RMAX + i, (r + 1) * RMAX + j);
            if (a1 <= b1) i++; else j++;
        }
    }
    __syncthreads();

    // Phase F: pixel counts per component (shared atomics)
    for (int g = tid; g < NRUNS; g += TMAIN) {
        int row = g >> 3, slot = g & (RMAX - 1);
        if (slot < sRunCnt[row]) {
            int A = sSE[g];
            atomicAdd(&cnt[uf_find(P, g)], (A & 0xffff) - (A >> 16) + 1);
        }
    }
    __syncthreads();

    // Phase G: argmax (count, tie -> smallest root id)
    {
        int bc = 0, br = 0x7fffffff;
        for (int g = tid; g < NRUNS; g += TMAIN) {
            int row = g >> 3, slot = g & (RMAX - 1);
            if (slot < sRunCnt[row]) {
                int cc = cnt[g];
                if (cc > bc || (cc == bc && g < br)) { bc = cc; br = g; }
            }
        }
        #pragma unroll
        for (int off = 16; off; off >>= 1) {
            int oc  = __shfl_down_sync(0xffffffffu, bc, off);
            int orr = __shfl_down_sync(0xffffffffu, br, off);
            if (oc > bc || (oc == bc && orr < br)) { bc = oc; br = orr; }
        }
        if ((tid & 31) == 0) { sBC[tid >> 5] = bc; sBR[tid >> 5] = br; }
        __syncthreads();
        if (tid == 0) {
            bc = sBC[0]; br = sBR[0];
            for (int j = 1; j < TMAIN / 32; j++) {
                if (sBC[j] > bc || (sBC[j] == bc && sBR[j] < br)) { bc = sBC[j]; br = sBR[j]; }
            }
            sBest = br; sBestCnt = bc;
        }
    }
    __syncthreads();

    // Phase H: bbox of largest component
    if (sBestCnt > 0) {
        int best = sBest;
        int rmin = HW, rmax = -1, cmin = HW, cmax = -1;
        for (int g = tid; g < NRUNS; g += TMAIN) {
            int row = g >> 3, slot = g & (RMAX - 1);
            if (slot < sRunCnt[row] && uf_find(P, g) == best) {
                int A = sSE[g];
                rmin = min(rmin, row); rmax = max(rmax, row);
                cmin = min(cmin, A >> 16); cmax = max(cmax, A & 0xffff);
            }
        }
        if (rmax >= 0) {
            atomicMin(&sRmin, rmin); atomicMax(&sRmax, rmax);
            atomicMin(&sCmin, cmin); atomicMax(&sCmax, cmax);
        }
    }
    __syncthreads();

    if (tid == 0) {
        int xmin = sRmin, xmax = sRmax, ymin = sCmin, ymax = sCmax;
        if (sBestCnt <= 0 || xmax < 0) { xmin = 0; ymin = 0; xmax = OUTD - 1; ymax = OUTD - 1; }
        sBox = make_int4(xmin, xmax, ymin, ymax);
        float* co = outCoords + n * 4;
        co[0] = (float)ymin; co[1] = (float)xmin;    // torch order [ymin,xmin,ymax,xmax]
        co[2] = (float)ymax; co[3] = (float)xmax;
    }
    __syncthreads();

    // Phase I: crop interpolation tables
    if (tid < OUTD) {
        int4 bx = sBox;
        int i = tid;
        float g = (float)i / 223.0f;
        int Lx = max(bx.y - bx.x, 1);
        float xs = __fadd_rn((float)bx.x, __fmul_rn(g, (float)(Lx - 1)));
        int x0 = min(max((int)floorf(xs), 0), 223);
        d_tr[n * OUTD + i] = make_float2(__int_as_float(x0), __fsub_rn(xs, (float)x0));
        int Ly = max(bx.w - bx.z, 1);
        float ys = __fadd_rn((float)bx.z, __fmul_rn(g, (float)(Ly - 1)));
        int y0 = min(max((int)floorf(ys), 0), 223);
        d_tc[n * OUTD + i] = make_float2(__int_as_float(y0), __fsub_rn(ys, (float)y0));
    }
}

// ---------------- kernel 3: band-tiled crop with source-row pre-blend (BAND=16) ----------------
// grid (14 bands, 3 ch, N), block 224. ~32 KB smem -> ~6 blocks/SM.
__global__ __launch_bounds__(224) void k_crop(const float* __restrict__ x,
                                              float* __restrict__ out)
{
    __shared__ __align__(16) float sImg[SROWS * OUTD + 4];
    __shared__ __align__(16) float sCB[SROWS * OUTD];       // col-blended source rows
    __shared__ float2 sTR[BAND];
    __shared__ int sLo, sRr;

    const int band = blockIdx.x, ch = blockIdx.y, n = blockIdx.z;
    const int tid = threadIdx.x;
    const int r0g = band * BAND;

    if (tid < BAND) sTR[tid] = d_tr[n * OUTD + r0g + tid];
    float2 tc = d_tc[n * OUTD + tid];            // this thread's column (phase A)
    const int y0 = __float_as_int(tc.x);
    const int y1 = min(y0 + 1, 223);
    const float wy = tc.y, iwy = __fsub_rn(1.f, wy);
    __syncthreads();
    if (tid == 0) {
        int lo = __float_as_int(sTR[0].x);
        int hi = min(__float_as_int(sTR[BAND - 1].x) + 1, 223);
        sLo = lo; sRr = hi - lo + 1;             // <= 17
    }
    __syncthreads();
    const int lo = sLo, R = sRr;

    const float* img = x + ((size_t)n * 3 + ch) * HW + lo * OUTD;
    for (int i = tid; i < R * OUTD; i += 224)
        sImg[i] = __ldg(&img[i]);                // fully coalesced strip load
    __syncthreads();

    // Phase A: column blend per source row (column fixed per thread)
    for (int xr = 0; xr < R; xr++) {
        const float* row = sImg + xr * OUTD;
        sCB[xr * OUTD + tid] =
            __fadd_rn(__fmul_rn(iwy, row[y0]), __fmul_rn(wy, row[y1]));
    }
    __syncthreads();

    // Phase B: row blend, 4-col groups, LDS.128 + STG.128
    const int c4 = tid % 56, rg = tid / 56;      // (4 row-slots) x (56 col-groups)
    const int c0 = c4 * 4;
    float* o = out + ((size_t)n * 3 + ch) * HW;
    #pragma unroll
    for (int j = 0; j < BAND / 4; j++) {         // 4 iterations
        int rl = rg + j * 4;                     // local row 0..15
        float2 tr = sTR[rl];
        int x0 = __float_as_int(tr.x);
        int x0l = x0 - lo;
        int x1l = min(x0 + 1, 223) - lo;
        float wx = tr.y, iwx = __fsub_rn(1.f, wx);
        float4 a = reinterpret_cast<const float4*>(sCB + x0l * OUTD)[c4];
        float4 b = reinterpret_cast<const float4*>(sCB + x1l * OUTD)[c4];
        float4 res;
        res.x = __fadd_rn(__fmul_rn(iwx, a.x), __fmul_rn(wx, b.x));
        res.y = __fadd_rn(__fmul_rn(iwx, a.y), __fmul_rn(wx, b.y));
        res.z = __fadd_rn(__fmul_rn(iwx, a.z), __fmul_rn(wx, b.z));
        res.w = __fadd_rn(__fmul_rn(iwx, a.w), __fmul_rn(wx, b.w));
        *reinterpret_cast<float4*>(o + (r0g + rl) * OUTD + c0) = res;
    }
}

// ---------------- launch ----------------
extern "C" void kernel_launch(void* const* d_in, const int* in_sizes, int n_in,
                              void* d_out, int out_size)
{
    const float* x    = (const float*)d_in[0];   // (N,3,224,224)
    const float* feat = (const float*)d_in[1];   // (N,2048,7,7)
    float* out = (float*)d_out;

    int N = in_sizes[0] / (3 * HW);
    if (N > NMAX) N = NMAX;

    float* outCrop   = out;
    float* outHeat   = out + (size_t)N * 3 * HW;
    float* outCoords = out + (size_t)N * 3 * HW + (size_t)N * HW;

    k_featmax<<<dim3(NSLICE, N), 784>>>(feat);
    k_main   <<<N, TMAIN, 3 * NRUNS * sizeof(int)>>>(outHeat, outCoords);
    k_crop   <<<dim3(OUTD / BAND, 3, N), 224>>>(x, outCrop);
}